// round 1
// baseline (speedup 1.0000x reference)
#include <cuda_runtime.h>

// GraphUpsamplingBlock collapses to a dense per-coarse-node 3-layer MLP:
//   H = relu(x[snd] @ W_emb[q])                (128 -> 64)
//   E = 0.25 * relu(H @ W_edge[q][2:66])       (64  -> 64)
//   O = relu(E @ W_node[128+64q : 128+64q+64]) (64  -> 256)
//   out[rcv - n_coarse] = O
// because receiver features / efeat are identically zero and the scatter is a
// permutation (each fine node has exactly one incoming edge, in one quadrant).

#define NCOARSE 55552   // 248*224
#define CDIM    128
#define UDIM    64
#define NUNITS  256
#define TILE_M  64
#define LDX     68      // padded lead dim for transposed tiles
#define LDH     68
#define NTHREADS 256

#define SMEM_FLOATS (CDIM*LDX + CDIM*UDIM + UDIM*UDIM + UDIM*NUNITS + 2*UDIM*LDH)

__global__ void __launch_bounds__(NTHREADS, 1)
gub_kernel(const float* __restrict__ x,
           const float* __restrict__ W_emb,
           const float* __restrict__ W_edge,
           const float* __restrict__ W_node,
           const int*   __restrict__ edge_idx,
           float* __restrict__ out)
{
    extern __shared__ float smem[];
    float* Xs    = smem;                       // [CDIM][LDX]   X^T tile
    float* Wemb  = Xs   + CDIM * LDX;          // [CDIM][UDIM]
    float* We    = Wemb + CDIM * UDIM;         // [UDIM][UDIM]
    float* Wn    = We   + UDIM * UDIM;         // [UDIM][NUNITS]
    float* Ht    = Wn   + UDIM * NUNITS;       // [UDIM][LDH]   H^T
    float* Et    = Ht   + UDIM * LDH;          // [UDIM][LDH]   E^T

    __shared__ int snd[TILE_M];
    __shared__ int rcv[TILE_M];

    const int tid = threadIdx.x;
    const int q   = blockIdx.y;
    const int m0  = blockIdx.x * TILE_M;

    // edge indices for this tile (sender = coarse node, receiver = fine node)
    if (tid < TILE_M) {
        int eoff = (q * NCOARSE + m0 + tid) * 2;
        snd[tid] = edge_idx[eoff];
        rcv[tid] = edge_idx[eoff + 1] - NCOARSE;
    }

    // weights for this quadrant
    const float* Wemb_g = W_emb + (size_t)q * CDIM * UDIM;
    for (int i = tid; i < CDIM * UDIM; i += NTHREADS) Wemb[i] = Wemb_g[i];
    const float* We_g = W_edge + (size_t)q * (2 + 2 * UDIM) * UDIM + 2 * UDIM;
    for (int i = tid; i < UDIM * UDIM; i += NTHREADS) We[i] = We_g[i];
    const float* Wn_g = W_node + (size_t)(CDIM + q * UDIM) * NUNITS;
    for (int i = tid; i < UDIM * NUNITS; i += NTHREADS) Wn[i] = Wn_g[i];

    __syncthreads();  // snd[] visible before X gather

    // X tile, stored transposed: Xs[k][m]
    for (int i = tid; i < TILE_M * CDIM; i += NTHREADS) {
        int r = i >> 7;        // / CDIM
        int k = i & (CDIM - 1);
        Xs[k * LDX + r] = x[(size_t)snd[r] * CDIM + k];
    }
    __syncthreads();

    // ---------------- GEMM1: H[64][64] = relu(X @ Wemb), write H^T ----------
    {
        const int ty = tid >> 4, tx = tid & 15;
        const int m = ty * 4, n = tx * 4;
        float acc[4][4];
        #pragma unroll
        for (int i = 0; i < 4; i++)
            #pragma unroll
            for (int j = 0; j < 4; j++) acc[i][j] = 0.f;

        #pragma unroll 4
        for (int k = 0; k < CDIM; k++) {
            float4 a = *(const float4*)&Xs[k * LDX + m];
            float4 b = *(const float4*)&Wemb[k * UDIM + n];
            float av[4] = {a.x, a.y, a.z, a.w};
            float bv[4] = {b.x, b.y, b.z, b.w};
            #pragma unroll
            for (int i = 0; i < 4; i++)
                #pragma unroll
                for (int j = 0; j < 4; j++) acc[i][j] = fmaf(av[i], bv[j], acc[i][j]);
        }
        #pragma unroll
        for (int j = 0; j < 4; j++)
            #pragma unroll
            for (int i = 0; i < 4; i++)
                Ht[(n + j) * LDH + (m + i)] = fmaxf(acc[i][j], 0.f);
    }
    __syncthreads();

    // ---------------- GEMM2: E[64][64] = 0.25*relu(H @ We), write E^T -------
    {
        const int ty = tid >> 4, tx = tid & 15;
        const int m = ty * 4, n = tx * 4;
        float acc[4][4];
        #pragma unroll
        for (int i = 0; i < 4; i++)
            #pragma unroll
            for (int j = 0; j < 4; j++) acc[i][j] = 0.f;

        #pragma unroll 4
        for (int k = 0; k < UDIM; k++) {
            float4 a = *(const float4*)&Ht[k * LDH + m];
            float4 b = *(const float4*)&We[k * UDIM + n];
            float av[4] = {a.x, a.y, a.z, a.w};
            float bv[4] = {b.x, b.y, b.z, b.w};
            #pragma unroll
            for (int i = 0; i < 4; i++)
                #pragma unroll
                for (int j = 0; j < 4; j++) acc[i][j] = fmaf(av[i], bv[j], acc[i][j]);
        }
        #pragma unroll
        for (int j = 0; j < 4; j++)
            #pragma unroll
            for (int i = 0; i < 4; i++)
                Et[(n + j) * LDH + (m + i)] = fmaxf(acc[i][j], 0.f) * 0.25f;
    }
    __syncthreads();

    // ---------------- GEMM3: O[64][256] = relu(E @ Wn), scatter to out -----
    {
        const int wy   = tid >> 5;   // warp id 0..7 -> rows m..m+7
        const int lane = tid & 31;   // lane -> cols c..c+7
        const int m = wy * 8, c = lane * 8;
        float acc[8][8];
        #pragma unroll
        for (int i = 0; i < 8; i++)
            #pragma unroll
            for (int j = 0; j < 8; j++) acc[i][j] = 0.f;

        #pragma unroll 4
        for (int k = 0; k < UDIM; k++) {
            float4 a0 = *(const float4*)&Et[k * LDH + m];
            float4 a1 = *(const float4*)&Et[k * LDH + m + 4];
            float4 b0 = *(const float4*)&Wn[k * NUNITS + c];
            float4 b1 = *(const float4*)&Wn[k * NUNITS + c + 4];
            float av[8] = {a0.x, a0.y, a0.z, a0.w, a1.x, a1.y, a1.z, a1.w};
            float bv[8] = {b0.x, b0.y, b0.z, b0.w, b1.x, b1.y, b1.z, b1.w};
            #pragma unroll
            for (int i = 0; i < 8; i++)
                #pragma unroll
                for (int j = 0; j < 8; j++) acc[i][j] = fmaf(av[i], bv[j], acc[i][j]);
        }

        #pragma unroll
        for (int i = 0; i < 8; i++) {
            size_t row = (size_t)rcv[m + i];
            float4 v0, v1;
            v0.x = fmaxf(acc[i][0], 0.f); v0.y = fmaxf(acc[i][1], 0.f);
            v0.z = fmaxf(acc[i][2], 0.f); v0.w = fmaxf(acc[i][3], 0.f);
            v1.x = fmaxf(acc[i][4], 0.f); v1.y = fmaxf(acc[i][5], 0.f);
            v1.z = fmaxf(acc[i][6], 0.f); v1.w = fmaxf(acc[i][7], 0.f);
            *(float4*)&out[row * NUNITS + c]     = v0;
            *(float4*)&out[row * NUNITS + c + 4] = v1;
        }
    }
}

extern "C" void kernel_launch(void* const* d_in, const int* in_sizes, int n_in,
                              void* d_out, int out_size)
{
    const float* x        = (const float*)d_in[0];
    const float* W_emb    = (const float*)d_in[1];
    const float* W_edge   = (const float*)d_in[2];
    const float* W_node   = (const float*)d_in[3];
    const int*   edge_idx = (const int*)d_in[4];
    float* out = (float*)d_out;

    size_t smem_bytes = SMEM_FLOATS * sizeof(float);  // 184320
    cudaFuncSetAttribute(gub_kernel,
                         cudaFuncAttributeMaxDynamicSharedMemorySize,
                         (int)smem_bytes);

    dim3 grid(NCOARSE / TILE_M, 4);  // 868 x 4
    gub_kernel<<<grid, NTHREADS, smem_bytes>>>(x, W_emb, W_edge, W_node,
                                               edge_idx, out);
}

// round 2
// speedup vs baseline: 2.5971x; 2.5971x over previous
#include <cuda_runtime.h>
#include <cstdint>

// GraphUpsamplingBlock == dense per-coarse-node 3-layer MLP (see round-0 notes):
//   H = relu(x[snd] @ W_emb[q])                (128 -> 64)
//   E = 0.25 * relu(H @ W_edge[q][2:66])       (64  -> 64)
//   O = relu(E @ W_node[128+64q : +64])        (64  -> 256)
//   out[rcv - n_coarse] = O
// This version runs all GEMMs on the tensor pipe via mma.sync tf32.

#define NCOARSE 55552   // 248*224
#define CDIM    128
#define UDIM    64
#define NUNITS  256
#define TILE_M  128
#define NTHREADS 256

// lead dims chosen for conflict-free fragment loads:
//  A-matrix loads need ld % 32 == 4 ; B-matrix loads need ld % 32 == 8
#define LDX  132
#define LDH  68
#define LDE  68
#define LDW1 72
#define LDW2 72
#define LDW3 264

// word offsets in dynamic smem (uint32 words)
#define OFF_X   0                          // 128*132 = 16896 words (H aliases: 128*68)
#define OFF_W1  (CDIM*LDX)                 // W_emb 128*72 = 9216 words (E aliases: 128*68)
#define OFF_W2  (OFF_W1 + CDIM*LDW1)       // W_edge slice 64*72 = 4608
#define OFF_W3  (OFF_W2 + UDIM*LDW2)       // W_node slice 64*264 = 16896
#define SMEM_WORDS (OFF_W3 + UDIM*LDW3)    // 47616 words = 190464 B

__device__ __forceinline__ uint32_t f2tf(float f) {
    uint32_t u;
    asm("cvt.rna.tf32.f32 %0, %1;" : "=r"(u) : "f"(f));
    return u;
}

__device__ __forceinline__ void mma8(float c[4], const uint32_t a[4],
                                     uint32_t b0, uint32_t b1) {
    asm volatile(
        "mma.sync.aligned.m16n8k8.row.col.f32.tf32.tf32.f32 "
        "{%0,%1,%2,%3},{%4,%5,%6,%7},{%8,%9},{%0,%1,%2,%3};"
        : "+f"(c[0]), "+f"(c[1]), "+f"(c[2]), "+f"(c[3])
        : "r"(a[0]), "r"(a[1]), "r"(a[2]), "r"(a[3]), "r"(b0), "r"(b1));
}

// load A fragment (16x8) from row-major tf32 smem
__device__ __forceinline__ void ldA(uint32_t a[4], const uint32_t* S, int ld,
                                    int mbase, int kk, int g, int tig) {
    a[0] = S[(mbase + g)     * ld + kk + tig];
    a[1] = S[(mbase + g + 8) * ld + kk + tig];
    a[2] = S[(mbase + g)     * ld + kk + tig + 4];
    a[3] = S[(mbase + g + 8) * ld + kk + tig + 4];
}
// load B fragment (8x8, K x N) from row-major tf32 smem
__device__ __forceinline__ void ldB(uint32_t& b0, uint32_t& b1, const uint32_t* S,
                                    int ld, int kk, int nbase, int g, int tig) {
    b0 = S[(kk + tig)     * ld + nbase + g];
    b1 = S[(kk + tig + 4) * ld + nbase + g];
}

__global__ void __launch_bounds__(NTHREADS, 1)
gub_tc_kernel(const float* __restrict__ x,
              const float* __restrict__ W_emb,
              const float* __restrict__ W_edge,
              const float* __restrict__ W_node,
              const int*   __restrict__ edge_idx,
              float* __restrict__ out)
{
    extern __shared__ uint32_t smem[];
    uint32_t* Xs   = smem + OFF_X;    // X tile  [128][LDX]  (tf32)
    uint32_t* Hs   = smem + OFF_X;    // H tile  [128][LDH]  (aliases X)
    uint32_t* W1s  = smem + OFF_W1;   // W_emb   [128][LDW1]
    uint32_t* Es   = smem + OFF_W1;   // E tile  [128][LDE]  (aliases W_emb)
    uint32_t* W2s  = smem + OFF_W2;   // W_edge  [64][LDW2]
    uint32_t* W3s  = smem + OFF_W3;   // W_node  [64][LDW3]

    __shared__ int snd[TILE_M];
    __shared__ int rcv[TILE_M];

    const int tid  = threadIdx.x;
    const int q    = blockIdx.y;
    const int m0t  = blockIdx.x * TILE_M;

    if (tid < TILE_M) {
        int eoff = (q * NCOARSE + m0t + tid) * 2;
        snd[tid] = edge_idx[eoff];
        rcv[tid] = edge_idx[eoff + 1] - NCOARSE;
    }

    // ---- stage weights (convert to tf32) ----
    const float* W1g = W_emb + (size_t)q * CDIM * UDIM;
    for (int i = tid; i < CDIM * UDIM; i += NTHREADS) {
        int r = i >> 6, c = i & 63;
        W1s[r * LDW1 + c] = f2tf(W1g[i]);
    }
    const float* W2g = W_edge + (size_t)q * (2 + 2 * UDIM) * UDIM + 2 * UDIM;
    for (int i = tid; i < UDIM * UDIM; i += NTHREADS) {
        int r = i >> 6, c = i & 63;
        W2s[r * LDW2 + c] = f2tf(W2g[i]);
    }
    const float* W3g = W_node + (size_t)(CDIM + q * UDIM) * NUNITS;
    for (int i = tid; i < UDIM * NUNITS; i += NTHREADS) {
        int r = i >> 8, c = i & 255;
        W3s[r * LDW3 + c] = f2tf(W3g[i]);
    }
    __syncthreads();  // snd[] visible

    // ---- gather X rows (float4 loads, convert to tf32) ----
    for (int i = tid; i < TILE_M * (CDIM / 4); i += NTHREADS) {
        int r  = i >> 5;          // / 32
        int c4 = (i & 31) << 2;
        float4 v = *(const float4*)&x[(size_t)snd[r] * CDIM + c4];
        uint32_t* dst = &Xs[r * LDX + c4];
        dst[0] = f2tf(v.x); dst[1] = f2tf(v.y);
        dst[2] = f2tf(v.z); dst[3] = f2tf(v.w);
    }
    __syncthreads();

    const int lane = tid & 31;
    const int warp = tid >> 5;
    const int g    = lane >> 2;
    const int tig  = lane & 3;
    const int wm   = warp & 3;     // row-pair index: rows 32*wm .. +31
    const int wn   = warp >> 2;    // col half
    const int mA   = 32 * wm;      // first 16-row tile
    const int mB   = 32 * wm + 16; // second

    // =================== GEMM1: H = relu(X @ W1), 128x64, K=128 ============
    {
        const int nb = 32 * wn;
        float acc[2][4][4];
        #pragma unroll
        for (int mt = 0; mt < 2; mt++)
            #pragma unroll
            for (int nt = 0; nt < 4; nt++)
                #pragma unroll
                for (int r = 0; r < 4; r++) acc[mt][nt][r] = 0.f;

        #pragma unroll
        for (int kh = 0; kh < 2; kh++) {
            uint32_t Af[2][8][4];
            #pragma unroll
            for (int ks = 0; ks < 8; ks++) {
                int kk = 64 * kh + 8 * ks;
                ldA(Af[0][ks], Xs, LDX, mA, kk, g, tig);
                ldA(Af[1][ks], Xs, LDX, mB, kk, g, tig);
            }
            #pragma unroll
            for (int ks = 0; ks < 8; ks++) {
                int kk = 64 * kh + 8 * ks;
                #pragma unroll
                for (int nt = 0; nt < 4; nt++) {
                    uint32_t b0, b1;
                    ldB(b0, b1, W1s, LDW1, kk, nb + 8 * nt, g, tig);
                    mma8(acc[0][nt], Af[0][ks], b0, b1);
                    mma8(acc[1][nt], Af[1][ks], b0, b1);
                }
            }
        }
        __syncthreads();  // everyone done reading Xs before H overwrites it
        #pragma unroll
        for (int mt = 0; mt < 2; mt++) {
            int mbase = mt ? mB : mA;
            #pragma unroll
            for (int nt = 0; nt < 4; nt++) {
                int c = nb + 8 * nt + 2 * tig;
                uint2 v0, v1;
                v0.x = f2tf(fmaxf(acc[mt][nt][0], 0.f));
                v0.y = f2tf(fmaxf(acc[mt][nt][1], 0.f));
                v1.x = f2tf(fmaxf(acc[mt][nt][2], 0.f));
                v1.y = f2tf(fmaxf(acc[mt][nt][3], 0.f));
                *(uint2*)&Hs[(mbase + g)     * LDH + c] = v0;
                *(uint2*)&Hs[(mbase + g + 8) * LDH + c] = v1;
            }
        }
    }
    __syncthreads();

    // =================== GEMM2: E = 0.25*relu(H @ W2), 128x64, K=64 ========
    {
        const int nb = 32 * wn;
        float acc[2][4][4];
        #pragma unroll
        for (int mt = 0; mt < 2; mt++)
            #pragma unroll
            for (int nt = 0; nt < 4; nt++)
                #pragma unroll
                for (int r = 0; r < 4; r++) acc[mt][nt][r] = 0.f;

        uint32_t Af[2][8][4];
        #pragma unroll
        for (int ks = 0; ks < 8; ks++) {
            ldA(Af[0][ks], Hs, LDH, mA, 8 * ks, g, tig);
            ldA(Af[1][ks], Hs, LDH, mB, 8 * ks, g, tig);
        }
        #pragma unroll
        for (int ks = 0; ks < 8; ks++) {
            #pragma unroll
            for (int nt = 0; nt < 4; nt++) {
                uint32_t b0, b1;
                ldB(b0, b1, W2s, LDW2, 8 * ks, nb + 8 * nt, g, tig);
                mma8(acc[0][nt], Af[0][ks], b0, b1);
                mma8(acc[1][nt], Af[1][ks], b0, b1);
            }
        }
        __syncthreads();  // done reading Hs & (earlier) W1s before E overwrites W1s
        #pragma unroll
        for (int mt = 0; mt < 2; mt++) {
            int mbase = mt ? mB : mA;
            #pragma unroll
            for (int nt = 0; nt < 4; nt++) {
                int c = nb + 8 * nt + 2 * tig;
                uint2 v0, v1;
                v0.x = f2tf(fmaxf(acc[mt][nt][0], 0.f) * 0.25f);
                v0.y = f2tf(fmaxf(acc[mt][nt][1], 0.f) * 0.25f);
                v1.x = f2tf(fmaxf(acc[mt][nt][2], 0.f) * 0.25f);
                v1.y = f2tf(fmaxf(acc[mt][nt][3], 0.f) * 0.25f);
                *(uint2*)&Es[(mbase + g)     * LDE + c] = v0;
                *(uint2*)&Es[(mbase + g + 8) * LDE + c] = v1;
            }
        }
    }
    __syncthreads();

    // =================== GEMM3: O = relu(E @ W3), 128x256, K=64, scatter ===
    {
        uint32_t Af[2][8][4];
        #pragma unroll
        for (int ks = 0; ks < 8; ks++) {
            ldA(Af[0][ks], Es, LDE, mA, 8 * ks, g, tig);
            ldA(Af[1][ks], Es, LDE, mB, 8 * ks, g, tig);
        }
        const int r0A = rcv[mA + g], r1A = rcv[mA + g + 8];
        const int r0B = rcv[mB + g], r1B = rcv[mB + g + 8];

        #pragma unroll
        for (int pass = 0; pass < 4; pass++) {
            const int nb = 128 * wn + 32 * pass;
            float acc[2][4][4];
            #pragma unroll
            for (int mt = 0; mt < 2; mt++)
                #pragma unroll
                for (int nt = 0; nt < 4; nt++)
                    #pragma unroll
                    for (int r = 0; r < 4; r++) acc[mt][nt][r] = 0.f;

            #pragma unroll
            for (int ks = 0; ks < 8; ks++) {
                #pragma unroll
                for (int nt = 0; nt < 4; nt++) {
                    uint32_t b0, b1;
                    ldB(b0, b1, W3s, LDW3, 8 * ks, nb + 8 * nt, g, tig);
                    mma8(acc[0][nt], Af[0][ks], b0, b1);
                    mma8(acc[1][nt], Af[1][ks], b0, b1);
                }
            }
            #pragma unroll
            for (int mt = 0; mt < 2; mt++) {
                int r0 = mt ? r0B : r0A;
                int r1 = mt ? r1B : r1A;
                #pragma unroll
                for (int nt = 0; nt < 4; nt++) {
                    int c = nb + 8 * nt + 2 * tig;
                    float2 v0, v1;
                    v0.x = fmaxf(acc[mt][nt][0], 0.f);
                    v0.y = fmaxf(acc[mt][nt][1], 0.f);
                    v1.x = fmaxf(acc[mt][nt][2], 0.f);
                    v1.y = fmaxf(acc[mt][nt][3], 0.f);
                    *(float2*)&out[(size_t)r0 * NUNITS + c] = v0;
                    *(float2*)&out[(size_t)r1 * NUNITS + c] = v1;
                }
            }
        }
    }
}

extern "C" void kernel_launch(void* const* d_in, const int* in_sizes, int n_in,
                              void* d_out, int out_size)
{
    const float* x        = (const float*)d_in[0];
    const float* W_emb    = (const float*)d_in[1];
    const float* W_edge   = (const float*)d_in[2];
    const float* W_node   = (const float*)d_in[3];
    const int*   edge_idx = (const int*)d_in[4];
    float* out = (float*)d_out;

    size_t smem_bytes = SMEM_WORDS * sizeof(uint32_t);  // 190464
    cudaFuncSetAttribute(gub_tc_kernel,
                         cudaFuncAttributeMaxDynamicSharedMemorySize,
                         (int)smem_bytes);

    dim3 grid(NCOARSE / TILE_M, 4);  // 434 x 4
    gub_tc_kernel<<<grid, NTHREADS, smem_bytes>>>(x, W_emb, W_edge, W_node,
                                                  edge_idx, out);
}

// round 3
// speedup vs baseline: 4.1600x; 1.6018x over previous
#include <cuda_runtime.h>
#include <cstdint>

// GraphUpsamplingBlock == dense per-coarse-node 3-layer MLP:
//   H = relu(x[snd] @ W_emb[q])                (128 -> 64)
//   E = 0.25 * relu(H @ W_edge[q][2:66])       (64  -> 64)
//   O = relu(E @ W_node[128+64q : +64])        (64  -> 256)
//   out[rcv - n_coarse] = O
// Persistent CTAs (weights staged once), tf32 mma, GEMM1 A direct from global.

#define NCOARSE 55552   // 248*224
#define CDIM    128
#define UDIM    64
#define NUNITS  256
#define TILE_M  128
#define NTILES  434     // NCOARSE / TILE_M
#define NTHREADS 512
#define NSLOTS  37      // grid = 4 * 37 = 148 persistent CTAs

// lead dims: A-loads need ld%32==4, B-loads need ld%32==8
#define LDH  68
#define LDW1 72
#define LDW2 72
#define LDW3 264

#define OFF_W1 0
#define OFF_W2 (OFF_W1 + CDIM*LDW1)        // 9216
#define OFF_W3 (OFF_W2 + UDIM*LDW2)        // 13824
#define OFF_HE (OFF_W3 + UDIM*LDW3)        // 30720
#define SMEM_WORDS (OFF_HE + TILE_M*LDH)   // 39424 words = 157696 B

__device__ __forceinline__ uint32_t f2tf(float f) {
    uint32_t u;
    asm("cvt.rna.tf32.f32 %0, %1;" : "=r"(u) : "f"(f));
    return u;
}

__device__ __forceinline__ void mma8(float c[4], const uint32_t a[4],
                                     uint32_t b0, uint32_t b1) {
    asm volatile(
        "mma.sync.aligned.m16n8k8.row.col.f32.tf32.tf32.f32 "
        "{%0,%1,%2,%3},{%4,%5,%6,%7},{%8,%9},{%0,%1,%2,%3};"
        : "+f"(c[0]), "+f"(c[1]), "+f"(c[2]), "+f"(c[3])
        : "r"(a[0]), "r"(a[1]), "r"(a[2]), "r"(a[3]), "r"(b0), "r"(b1));
}

__device__ __forceinline__ void ldA(uint32_t a[4], const uint32_t* S, int ld,
                                    int mbase, int kk, int g, int tig) {
    a[0] = S[(mbase + g)     * ld + kk + tig];
    a[1] = S[(mbase + g + 8) * ld + kk + tig];
    a[2] = S[(mbase + g)     * ld + kk + tig + 4];
    a[3] = S[(mbase + g + 8) * ld + kk + tig + 4];
}

__global__ void __launch_bounds__(NTHREADS, 1)
gub_tc2_kernel(const float* __restrict__ x,
               const float* __restrict__ W_emb,
               const float* __restrict__ W_edge,
               const float* __restrict__ W_node,
               const int*   __restrict__ edge_idx,
               float* __restrict__ out)
{
    extern __shared__ uint32_t smem[];
    uint32_t* W1s = smem + OFF_W1;   // [128][LDW1]
    uint32_t* W2s = smem + OFF_W2;   // [64][LDW2]
    uint32_t* W3s = smem + OFF_W3;   // [64][LDW3]
    uint32_t* HEs = smem + OFF_HE;   // [128][LDH]  (H, then E)

    __shared__ int snd[TILE_M];
    __shared__ int rcv[TILE_M];

    const int tid  = threadIdx.x;
    const int q    = blockIdx.x & 3;
    const int slot = blockIdx.x >> 2;

    // ---- stage weights ONCE per CTA (convert to tf32) ----
    const float* W1g = W_emb + (size_t)q * CDIM * UDIM;
    for (int i = tid; i < CDIM * UDIM; i += NTHREADS)
        W1s[(i >> 6) * LDW1 + (i & 63)] = f2tf(W1g[i]);
    const float* W2g = W_edge + (size_t)q * (2 + 2 * UDIM) * UDIM + 2 * UDIM;
    for (int i = tid; i < UDIM * UDIM; i += NTHREADS)
        W2s[(i >> 6) * LDW2 + (i & 63)] = f2tf(W2g[i]);
    const float* W3g = W_node + (size_t)(CDIM + q * UDIM) * NUNITS;
    for (int i = tid; i < UDIM * NUNITS; i += NTHREADS)
        W3s[(i >> 8) * LDW3 + (i & 255)] = f2tf(W3g[i]);

    const int lane = tid & 31;
    const int warp = tid >> 5;
    const int g    = lane >> 2;
    const int tig  = lane & 3;
    const int wr   = warp & 7;     // 8 row groups of 16
    const int wc   = warp >> 3;    // 2 col halves
    const int mb   = 16 * wr;
    const int nb   = 32 * wc;

    for (int t = slot; t < NTILES; t += NSLOTS) {
        const int m0 = t * TILE_M;
        if (tid < TILE_M) {
            int eoff = (q * NCOARSE + m0 + tid) * 2;
            snd[tid] = edge_idx[eoff];
            rcv[tid] = edge_idx[eoff + 1] - NCOARSE;
        }
        __syncthreads();   // idx visible; weights visible (1st iter);
                           // all warps past previous tile's GEMM3 (E reads done)

        // consume indices into registers early (avoids races with next-iter writes)
        const int r0 = rcv[mb + g], r1 = rcv[mb + g + 8];
        const float* xr0 = x + (size_t)snd[mb + g]     * CDIM;
        const float* xr1 = x + (size_t)snd[mb + g + 8] * CDIM;

        // =========== GEMM1: H = relu(X @ W1), 128x64, K=128, A from global ==
        {
            float acc[4][4];
            #pragma unroll
            for (int nt = 0; nt < 4; nt++)
                #pragma unroll
                for (int r = 0; r < 4; r++) acc[nt][r] = 0.f;

            #pragma unroll
            for (int kh = 0; kh < 2; kh++) {
                uint32_t Af[8][4];
                #pragma unroll
                for (int ks = 0; ks < 8; ks++) {
                    int kk = 64 * kh + 8 * ks;
                    Af[ks][0] = f2tf(__ldg(&xr0[kk + tig]));
                    Af[ks][1] = f2tf(__ldg(&xr1[kk + tig]));
                    Af[ks][2] = f2tf(__ldg(&xr0[kk + tig + 4]));
                    Af[ks][3] = f2tf(__ldg(&xr1[kk + tig + 4]));
                }
                #pragma unroll
                for (int ks = 0; ks < 8; ks++) {
                    int kk = 64 * kh + 8 * ks;
                    #pragma unroll
                    for (int nt = 0; nt < 4; nt++) {
                        uint32_t b0 = W1s[(kk + tig)     * LDW1 + nb + 8 * nt + g];
                        uint32_t b1 = W1s[(kk + tig + 4) * LDW1 + nb + 8 * nt + g];
                        mma8(acc[nt], Af[ks], b0, b1);
                    }
                }
            }
            // store H^ (tf32) — safe: loop-top barrier guaranteed E reads done
            #pragma unroll
            for (int nt = 0; nt < 4; nt++) {
                int c = nb + 8 * nt + 2 * tig;
                uint2 v0, v1;
                v0.x = f2tf(fmaxf(acc[nt][0], 0.f));
                v0.y = f2tf(fmaxf(acc[nt][1], 0.f));
                v1.x = f2tf(fmaxf(acc[nt][2], 0.f));
                v1.y = f2tf(fmaxf(acc[nt][3], 0.f));
                *(uint2*)&HEs[(mb + g)     * LDH + c] = v0;
                *(uint2*)&HEs[(mb + g + 8) * LDH + c] = v1;
            }
        }
        __syncthreads();

        // =========== GEMM2: E = 0.25*relu(H @ W2), 128x64, K=64 =============
        {
            float acc[4][4];
            #pragma unroll
            for (int nt = 0; nt < 4; nt++)
                #pragma unroll
                for (int r = 0; r < 4; r++) acc[nt][r] = 0.f;

            uint32_t Af[8][4];
            #pragma unroll
            for (int ks = 0; ks < 8; ks++)
                ldA(Af[ks], HEs, LDH, mb, 8 * ks, g, tig);
            #pragma unroll
            for (int ks = 0; ks < 8; ks++) {
                #pragma unroll
                for (int nt = 0; nt < 4; nt++) {
                    uint32_t b0 = W2s[(8 * ks + tig)     * LDW2 + nb + 8 * nt + g];
                    uint32_t b1 = W2s[(8 * ks + tig + 4) * LDW2 + nb + 8 * nt + g];
                    mma8(acc[nt], Af[ks], b0, b1);
                }
            }
            __syncthreads();   // all H reads done before E overwrites buffer
            #pragma unroll
            for (int nt = 0; nt < 4; nt++) {
                int c = nb + 8 * nt + 2 * tig;
                uint2 v0, v1;
                v0.x = f2tf(fmaxf(acc[nt][0], 0.f) * 0.25f);
                v0.y = f2tf(fmaxf(acc[nt][1], 0.f) * 0.25f);
                v1.x = f2tf(fmaxf(acc[nt][2], 0.f) * 0.25f);
                v1.y = f2tf(fmaxf(acc[nt][3], 0.f) * 0.25f);
                *(uint2*)&HEs[(mb + g)     * LDH + c] = v0;
                *(uint2*)&HEs[(mb + g + 8) * LDH + c] = v1;
            }
        }
        __syncthreads();

        // =========== GEMM3: O = relu(E @ W3), 128x256, K=64, scatter ========
        {
            uint32_t Af[8][4];
            #pragma unroll
            for (int ks = 0; ks < 8; ks++)
                ldA(Af[ks], HEs, LDH, mb, 8 * ks, g, tig);

            #pragma unroll
            for (int pass = 0; pass < 2; pass++) {
                const int cb = 128 * wc + 64 * pass;
                float acc[8][4];
                #pragma unroll
                for (int nt = 0; nt < 8; nt++)
                    #pragma unroll
                    for (int r = 0; r < 4; r++) acc[nt][r] = 0.f;

                #pragma unroll
                for (int ks = 0; ks < 8; ks++) {
                    #pragma unroll
                    for (int nt = 0; nt < 8; nt++) {
                        uint32_t b0 = W3s[(8 * ks + tig)     * LDW3 + cb + 8 * nt + g];
                        uint32_t b1 = W3s[(8 * ks + tig + 4) * LDW3 + cb + 8 * nt + g];
                        mma8(acc[nt], Af[ks], b0, b1);
                    }
                }
                #pragma unroll
                for (int nt = 0; nt < 8; nt++) {
                    int c = cb + 8 * nt + 2 * tig;
                    float2 v0, v1;
                    v0.x = fmaxf(acc[nt][0], 0.f);
                    v0.y = fmaxf(acc[nt][1], 0.f);
                    v1.x = fmaxf(acc[nt][2], 0.f);
                    v1.y = fmaxf(acc[nt][3], 0.f);
                    *(float2*)&out[(size_t)r0 * NUNITS + c] = v0;
                    *(float2*)&out[(size_t)r1 * NUNITS + c] = v1;
                }
            }
        }
        // no sync here: loop-top barrier protects snd/rcv & HE reuse
    }
}

extern "C" void kernel_launch(void* const* d_in, const int* in_sizes, int n_in,
                              void* d_out, int out_size)
{
    const float* x        = (const float*)d_in[0];
    const float* W_emb    = (const float*)d_in[1];
    const float* W_edge   = (const float*)d_in[2];
    const float* W_node   = (const float*)d_in[3];
    const int*   edge_idx = (const int*)d_in[4];
    float* out = (float*)d_out;

    size_t smem_bytes = SMEM_WORDS * sizeof(uint32_t);  // 157696
    cudaFuncSetAttribute(gub_tc2_kernel,
                         cudaFuncAttributeMaxDynamicSharedMemorySize,
                         (int)smem_bytes);

    gub_tc2_kernel<<<4 * NSLOTS, NTHREADS, smem_bytes>>>(x, W_emb, W_edge,
                                                         W_node, edge_idx, out);
}

// round 4
// speedup vs baseline: 4.4018x; 1.0581x over previous
#include <cuda_runtime.h>
#include <cstdint>

// GraphUpsamplingBlock == dense per-coarse-node 3-layer MLP:
//   H = relu(x[snd] @ W_emb[q])                (128 -> 64)
//   E = 0.25 * relu(H @ W_edge[q][2:66])       (64  -> 64)
//   O = relu(E @ W_node[128+64q : +64])        (64  -> 256)
//   out[rcv - n_coarse] = O
// Persistent CTAs, tf32 mma, ldmatrix fragment loads, 2 barriers/tile.

#define NCOARSE 55552   // 248*224
#define CDIM    128
#define UDIM    64
#define NUNITS  256
#define TILE_M  128
#define NTILES  434     // NCOARSE / TILE_M
#define NTHREADS 512
#define NSLOTS  37      // grid = 4 * 37 = 148 persistent CTAs

// transposed weights: Wt[n][k], ld % 8 == 4 for conflict-free ldmatrix
#define LDW1T 132
#define LDW2T 68
#define LDW3T 68
#define LDHE  68

#define OFF_W1T 0
#define OFF_W2T (OFF_W1T + UDIM*LDW1T)          // 8448
#define OFF_W3T (OFF_W2T + UDIM*LDW2T)          // 12800
#define OFF_HA  (OFF_W3T + NUNITS*LDW3T)        // 30208
#define OFF_HB  (OFF_HA + TILE_M*LDHE)          // 38912
#define SMEM_WORDS (OFF_HB + TILE_M*LDHE)       // 47616 words = 190464 B

__device__ __forceinline__ uint32_t f2tf(float f) {
    uint32_t u;
    asm("cvt.rna.tf32.f32 %0, %1;" : "=r"(u) : "f"(f));
    return u;
}

__device__ __forceinline__ void mma8(float c[4], const uint32_t a0, const uint32_t a1,
                                     const uint32_t a2, const uint32_t a3,
                                     uint32_t b0, uint32_t b1) {
    asm volatile(
        "mma.sync.aligned.m16n8k8.row.col.f32.tf32.tf32.f32 "
        "{%0,%1,%2,%3},{%4,%5,%6,%7},{%8,%9},{%0,%1,%2,%3};"
        : "+f"(c[0]), "+f"(c[1]), "+f"(c[2]), "+f"(c[3])
        : "r"(a0), "r"(a1), "r"(a2), "r"(a3), "r"(b0), "r"(b1));
}

__device__ __forceinline__ void ldm4(uint32_t r[4], uint32_t saddr) {
    asm volatile("ldmatrix.sync.aligned.m8n8.x4.shared.b16 {%0,%1,%2,%3}, [%4];"
        : "=r"(r[0]), "=r"(r[1]), "=r"(r[2]), "=r"(r[3]) : "r"(saddr));
}

__global__ void __launch_bounds__(NTHREADS, 1)
gub_tc3_kernel(const float* __restrict__ x,
               const float* __restrict__ W_emb,
               const float* __restrict__ W_edge,
               const float* __restrict__ W_node,
               const int*   __restrict__ edge_idx,
               float* __restrict__ out)
{
    extern __shared__ uint32_t smem[];
    uint32_t* W1t = smem + OFF_W1T;   // [64 n][LDW1T]  (k contiguous)
    uint32_t* W2t = smem + OFF_W2T;   // [64 n][LDW2T]
    uint32_t* W3t = smem + OFF_W3T;   // [256 n][LDW3T]
    uint32_t* Ha  = smem + OFF_HA;    // [128][LDHE]  H buffer
    uint32_t* Hb  = smem + OFF_HB;    // [128][LDHE]  E buffer

    __shared__ int sndb[2][TILE_M];
    __shared__ int rcvb[2][TILE_M];

    const int tid  = threadIdx.x;
    const int q    = blockIdx.x & 3;
    const int slot = blockIdx.x >> 2;

    // ---- stage transposed weights ONCE per CTA ----
    const float* W1g = W_emb + (size_t)q * CDIM * UDIM;            // [k][n]
    for (int i = tid; i < CDIM * UDIM; i += NTHREADS)
        W1t[(i & 63) * LDW1T + (i >> 6)] = f2tf(W1g[i]);
    const float* W2g = W_edge + (size_t)q * (2 + 2 * UDIM) * UDIM + 2 * UDIM;
    for (int i = tid; i < UDIM * UDIM; i += NTHREADS)
        W2t[(i & 63) * LDW2T + (i >> 6)] = f2tf(W2g[i]);
    const float* W3g = W_node + (size_t)(CDIM + q * UDIM) * NUNITS; // [k][n]
    for (int i = tid; i < UDIM * NUNITS; i += NTHREADS)
        W3t[(i & 255) * LDW3T + (i >> 8)] = f2tf(W3g[i]);

    // first tile's edge indices
    if (tid < TILE_M) {
        int eoff = (q * NCOARSE + slot * TILE_M + tid) * 2;
        sndb[0][tid] = edge_idx[eoff];
        rcvb[0][tid] = edge_idx[eoff + 1] - NCOARSE;
    }
    __syncthreads();

    const int lane = tid & 31;
    const int warp = tid >> 5;
    const int g    = lane >> 2;
    const int tig  = lane & 3;
    const int wr   = warp & 7;     // 8 row groups of 16
    const int wc   = warp >> 3;    // 2 col halves
    const int mb   = 16 * wr;
    const int nb   = 32 * wc;

    // per-lane ldmatrix address patterns
    const uint32_t smem_u = (uint32_t)__cvta_generic_to_shared(smem);
    const int arow   = (lane & 7) + ((lane >> 3) & 1) * 8;
    const int acol   = (lane >> 4) * 4;
    const int a_pat  = (mb + arow) * LDHE + acol;
    const uint32_t aA = smem_u + 4u * (OFF_HA + a_pat);   // + 4*kk
    const uint32_t aB = smem_u + 4u * (OFF_HB + a_pat);
    const int brow   = lane & 7;
    const int bcol   = (lane >> 3) * 4;
    const uint32_t b1a = smem_u + 4u * (OFF_W1T + brow * LDW1T + bcol);
    const uint32_t b2a = smem_u + 4u * (OFF_W2T + brow * LDW2T + bcol);
    const uint32_t b3a = smem_u + 4u * (OFF_W3T + brow * LDW3T + bcol);

    int it = 0;
    for (int t = slot; t < NTILES; t += NSLOTS, ++it) {
        const int par = it & 1;
        const int r0 = rcvb[par][mb + g], r1 = rcvb[par][mb + g + 8];
        const float* xr0 = x + (size_t)sndb[par][mb + g]     * CDIM;
        const float* xr1 = x + (size_t)sndb[par][mb + g + 8] * CDIM;

        // prefetch next tile's edge indices (other buffer; no barrier needed)
        int t2 = t + NSLOTS;
        if (t2 < NTILES && tid < TILE_M) {
            int eoff = (q * NCOARSE + t2 * TILE_M + tid) * 2;
            sndb[par ^ 1][tid] = edge_idx[eoff];
            rcvb[par ^ 1][tid] = edge_idx[eoff + 1] - NCOARSE;
        }

        // =========== GEMM1: H = relu(X @ W1), A from global ================
        {
            float acc[4][4];
            #pragma unroll
            for (int nt = 0; nt < 4; nt++)
                #pragma unroll
                for (int r = 0; r < 4; r++) acc[nt][r] = 0.f;

            #pragma unroll
            for (int kh = 0; kh < 2; kh++) {
                uint32_t Af[8][4];
                #pragma unroll
                for (int ks = 0; ks < 8; ks++) {
                    int kk = 64 * kh + 8 * ks;
                    Af[ks][0] = f2tf(__ldg(&xr0[kk + tig]));
                    Af[ks][1] = f2tf(__ldg(&xr1[kk + tig]));
                    Af[ks][2] = f2tf(__ldg(&xr0[kk + tig + 4]));
                    Af[ks][3] = f2tf(__ldg(&xr1[kk + tig + 4]));
                }
                #pragma unroll
                for (int kp = 0; kp < 4; kp++) {
                    int kk = 64 * kh + 16 * kp;
                    #pragma unroll
                    for (int nt = 0; nt < 4; nt++) {
                        uint32_t bf[4];
                        ldm4(bf, b1a + 4u * ((nb + 8 * nt) * LDW1T + kk));
                        mma8(acc[nt], Af[2*kp][0],   Af[2*kp][1],   Af[2*kp][2],   Af[2*kp][3],   bf[0], bf[1]);
                        mma8(acc[nt], Af[2*kp+1][0], Af[2*kp+1][1], Af[2*kp+1][2], Af[2*kp+1][3], bf[2], bf[3]);
                    }
                }
            }
            #pragma unroll
            for (int nt = 0; nt < 4; nt++) {
                int c = nb + 8 * nt + 2 * tig;
                uint2 v0, v1;
                v0.x = f2tf(fmaxf(acc[nt][0], 0.f));
                v0.y = f2tf(fmaxf(acc[nt][1], 0.f));
                v1.x = f2tf(fmaxf(acc[nt][2], 0.f));
                v1.y = f2tf(fmaxf(acc[nt][3], 0.f));
                *(uint2*)&Ha[(mb + g)     * LDHE + c] = v0;
                *(uint2*)&Ha[(mb + g + 8) * LDHE + c] = v1;
            }
        }
        __syncthreads();   // H ready (also fences prev tile's E reads vs new E writes)

        // =========== GEMM2: E = 0.25*relu(H @ W2) ==========================
        {
            float acc[4][4];
            #pragma unroll
            for (int nt = 0; nt < 4; nt++)
                #pragma unroll
                for (int r = 0; r < 4; r++) acc[nt][r] = 0.f;

            uint32_t Af[8][4];
            #pragma unroll
            for (int ks = 0; ks < 8; ks++)
                ldm4(Af[ks], aA + 4u * (8 * ks));
            #pragma unroll
            for (int kp = 0; kp < 4; kp++) {
                #pragma unroll
                for (int nt = 0; nt < 4; nt++) {
                    uint32_t bf[4];
                    ldm4(bf, b2a + 4u * ((nb + 8 * nt) * LDW2T + 16 * kp));
                    mma8(acc[nt], Af[2*kp][0],   Af[2*kp][1],   Af[2*kp][2],   Af[2*kp][3],   bf[0], bf[1]);
                    mma8(acc[nt], Af[2*kp+1][0], Af[2*kp+1][1], Af[2*kp+1][2], Af[2*kp+1][3], bf[2], bf[3]);
                }
            }
            #pragma unroll
            for (int nt = 0; nt < 4; nt++) {
                int c = nb + 8 * nt + 2 * tig;
                uint2 v0, v1;
                v0.x = f2tf(fmaxf(acc[nt][0], 0.f) * 0.25f);
                v0.y = f2tf(fmaxf(acc[nt][1], 0.f) * 0.25f);
                v1.x = f2tf(fmaxf(acc[nt][2], 0.f) * 0.25f);
                v1.y = f2tf(fmaxf(acc[nt][3], 0.f) * 0.25f);
                *(uint2*)&Hb[(mb + g)     * LDHE + c] = v0;
                *(uint2*)&Hb[(mb + g + 8) * LDHE + c] = v1;
            }
        }
        __syncthreads();   // E ready

        // =========== GEMM3: O = relu(E @ W3), scatter ======================
        {
            uint32_t Af[8][4];
            #pragma unroll
            for (int ks = 0; ks < 8; ks++)
                ldm4(Af[ks], aB + 4u * (8 * ks));

            #pragma unroll
            for (int pass = 0; pass < 2; pass++) {
                const int cb = 128 * wc + 64 * pass;
                float acc[8][4];
                #pragma unroll
                for (int nt = 0; nt < 8; nt++)
                    #pragma unroll
                    for (int r = 0; r < 4; r++) acc[nt][r] = 0.f;

                #pragma unroll
                for (int kp = 0; kp < 4; kp++) {
                    #pragma unroll
                    for (int nt = 0; nt < 8; nt++) {
                        uint32_t bf[4];
                        ldm4(bf, b3a + 4u * ((cb + 8 * nt) * LDW3T + 16 * kp));
                        mma8(acc[nt], Af[2*kp][0],   Af[2*kp][1],   Af[2*kp][2],   Af[2*kp][3],   bf[0], bf[1]);
                        mma8(acc[nt], Af[2*kp+1][0], Af[2*kp+1][1], Af[2*kp+1][2], Af[2*kp+1][3], bf[2], bf[3]);
                    }
                }
                #pragma unroll
                for (int nt = 0; nt < 8; nt++) {
                    int c = cb + 8 * nt + 2 * tig;
                    float2 v0, v1;
                    v0.x = fmaxf(acc[nt][0], 0.f);
                    v0.y = fmaxf(acc[nt][1], 0.f);
                    v1.x = fmaxf(acc[nt][2], 0.f);
                    v1.y = fmaxf(acc[nt][3], 0.f);
                    *(float2*)&out[(size_t)r0 * NUNITS + c] = v0;
                    *(float2*)&out[(size_t)r1 * NUNITS + c] = v1;
                }
            }
        }
        // no trailing barrier: next iteration's sync1 fences all buffer reuse
    }
}

extern "C" void kernel_launch(void* const* d_in, const int* in_sizes, int n_in,
                              void* d_out, int out_size)
{
    const float* x        = (const float*)d_in[0];
    const float* W_emb    = (const float*)d_in[1];
    const float* W_edge   = (const float*)d_in[2];
    const float* W_node   = (const float*)d_in[3];
    const int*   edge_idx = (const int*)d_in[4];
    float* out = (float*)d_out;

    size_t smem_bytes = SMEM_WORDS * sizeof(uint32_t);  // 190464
    cudaFuncSetAttribute(gub_tc3_kernel,
                         cudaFuncAttributeMaxDynamicSharedMemorySize,
                         (int)smem_bytes);

    gub_tc3_kernel<<<4 * NSLOTS, NTHREADS, smem_bytes>>>(x, W_emb, W_edge,
                                                         W_node, edge_idx, out);
}